// round 1
// baseline (speedup 1.0000x reference)
#include <cuda_runtime.h>
#include <cuda_bf16.h>

#define NB   16384
#define NE   8
#define DIN  900
#define DM   512
#define DSEL 128
#define EPSF 1e-9f

#define OUT_GUIDE (NB * DM)        // 8388608
#define OUT_SEL   (NB * DM + 1)    // 8388609

// Scratch: per-(token,slot) expert output (gate-scaled), slot in {0,1}.
__device__ float g_scratch[(size_t)2 * NB * DM];   // 64 MB
__device__ int   g_bucket[NE * NB];                // token*2+slot entries per expert
__device__ int   g_count[NE];
__device__ float g_gate[2 * NB];                   // gate per (token,slot); 0 if unused
__device__ float g_partial[512];                   // guide-loss partial sums

// ---------------------------------------------------------------------------
__global__ void init_kernel() {
    int t = threadIdx.x;
    if (t < NE) g_count[t] = 0;
}

// ---------------------------------------------------------------------------
// Phase A: one warp per row. Softmax, inactive mixture -> selection embedding,
// top-2 gates, guide partials, expert bucketing (block-aggregated atomics).
__global__ void __launch_bounds__(1024) phaseA_kernel(
    const float* __restrict__ logits,
    const int*   __restrict__ masks,
    const float* __restrict__ selemb,
    float*       __restrict__ out)
{
    __shared__ int   lcount[NE];
    __shared__ int   lbase[NE];
    __shared__ int   staging[NE][32];
    __shared__ float warpS[32];

    int tid  = threadIdx.x;
    int warp = tid >> 5;
    int lane = tid & 31;
    if (tid < NE) lcount[tid] = 0;
    __syncthreads();

    int b = blockIdx.x * 32 + warp;

    float raw[NE];
    float mx = -1e30f;
#pragma unroll
    for (int e = 0; e < NE; e++) { raw[e] = logits[b * NE + e]; mx = fmaxf(mx, raw[e]); }
    float sum = 0.f;
#pragma unroll
    for (int e = 0; e < NE; e++) { raw[e] = expf(raw[e] - mx); sum += raw[e]; }
    float inv = 1.f / sum;
    int m[NE];
#pragma unroll
    for (int e = 0; e < NE; e++) { raw[e] *= inv; m[e] = masks[b * NE + e]; }

    // inactive-expert mixture weights
    float w[NE]; float isum = 0.f;
#pragma unroll
    for (int e = 0; e < NE; e++) { w[e] = (m[e] == 1) ? 0.f : raw[e]; isum += w[e]; }
    float winv = 1.f / (isum + EPSF);

    // active gates + guide partial
    float a[NE]; float srow = 0.f;
#pragma unroll
    for (int e = 0; e < NE; e++) {
        w[e] *= winv;
        a[e] = (m[e] == 1) ? raw[e] : 0.f;
        srow += a[e];
    }

    // top-2 (lowest index wins ties, matching jax.lax.top_k)
    float v1 = -1.f, v2 = -1.f; int e1 = 0, e2 = 0;
#pragma unroll
    for (int e = 0; e < NE; e++) {
        if (a[e] > v1) { v2 = v1; e2 = e1; v1 = a[e]; e1 = e; }
        else if (a[e] > v2) { v2 = a[e]; e2 = e; }
    }
    float gs = 1.f / (v1 + v2 + EPSF);
    float g1 = v1 * gs, g2 = v2 * gs;

    // selection embedding: each lane handles 4 consecutive s positions
    const float4* base = (const float4*)(selemb + (size_t)b * NE * DSEL);
    float4 acc = make_float4(0.f, 0.f, 0.f, 0.f);
#pragma unroll
    for (int e = 0; e < NE; e++) {
        float4 v = base[e * (DSEL / 4) + lane];
        acc.x += w[e] * v.x; acc.y += w[e] * v.y;
        acc.z += w[e] * v.z; acc.w += w[e] * v.w;
    }
    // OUT_SEL is an odd float offset -> scalar stores (16B misaligned)
    float* dst = out + OUT_SEL + (size_t)b * DSEL + lane * 4;
    dst[0] = acc.x; dst[1] = acc.y; dst[2] = acc.z; dst[3] = acc.w;

    if (lane == 0) {
        g_gate[2 * b]     = g1;
        g_gate[2 * b + 1] = g2;
        if (g1 > 0.f) { int p = atomicAdd(&lcount[e1], 1); staging[e1][p] = 2 * b; }
        if (g2 > 0.f) { int p = atomicAdd(&lcount[e2], 1); staging[e2][p] = 2 * b + 1; }
        warpS[warp] = srow;
    }
    __syncthreads();
    if (tid < NE) lbase[tid] = atomicAdd(&g_count[tid], lcount[tid]);
    if (tid == 0) {
        float s = 0.f;
        for (int i = 0; i < 32; i++) s += warpS[i];
        g_partial[blockIdx.x] = s;
    }
    __syncthreads();
#pragma unroll
    for (int e = 0; e < NE; e++) {
        for (int i = tid; i < lcount[e]; i += blockDim.x)
            g_bucket[e * NB + lbase[e] + i] = staging[e][i];
    }
}

// ---------------------------------------------------------------------------
__global__ void guide_kernel(float* __restrict__ out) {
    __shared__ float sm[512];
    int t = threadIdx.x;
    sm[t] = g_partial[t];
    __syncthreads();
    for (int s = 256; s > 0; s >>= 1) {
        if (t < s) sm[t] += sm[t + s];
        __syncthreads();
    }
    if (t == 0) {
        float sv = sm[0] / (float)NB;
        float d = 1.f - sv;
        out[OUT_GUIDE] = d * d;
    }
}

// ---------------------------------------------------------------------------
// Grouped SGEMM: per expert, gather 64 tokens x 64 cols, K=900 in 16-steps.
// 256 threads, 4x4 micro-tile per thread, register double-buffered gmem loads.
__global__ void __launch_bounds__(256) gemm_kernel(
    const float* __restrict__ X,
    const float* __restrict__ W,
    const float* __restrict__ bias)
{
    int e   = blockIdx.z;
    int cnt = g_count[e];
    int rt0 = blockIdx.x * 64;
    if (rt0 >= cnt) return;
    int rows = cnt - rt0; if (rows > 64) rows = 64;
    int n0 = blockIdx.y * 64;

    __shared__ float As[16 * 68];   // [k][row], padded
    __shared__ float Bs[16 * 64];   // [k][col]
    __shared__ int   sEntry[64];
    __shared__ float sGate[64];
    __shared__ float sBias[64];

    int t = threadIdx.x;
    if (t < 64) {
        int entry = 0; float g = 0.f;
        if (t < rows) { entry = g_bucket[e * NB + rt0 + t]; g = g_gate[entry]; }
        sEntry[t] = entry;
        sGate[t]  = g;
        sBias[t]  = bias[e * DM + n0 + t];
    }
    __syncthreads();

    // A loader mapping: 256 threads -> 64 rows x 4 float4 along k
    int ar = t >> 2, aq = t & 3;
    bool aValid = (ar < rows);
    const float* Abase = X + (size_t)(sEntry[ar] >> 1) * DIN + aq * 4;
    // B loader mapping: 256 threads -> 16 k-rows x 16 float4 along n
    int brow = t >> 4, bcol4 = (t & 15) << 2;
    const float* Bbase = W + (size_t)e * DIN * DM + (size_t)brow * DM + n0 + bcol4;

    int tx = t & 15, ty = t >> 4;
    float acc[4][4];
#pragma unroll
    for (int i = 0; i < 4; i++)
#pragma unroll
        for (int j = 0; j < 4; j++) acc[i][j] = 0.f;

    float4 aReg = make_float4(0.f, 0.f, 0.f, 0.f);
    float4 bReg = make_float4(0.f, 0.f, 0.f, 0.f);
    if (aValid) aReg = *(const float4*)Abase;     // k0 = 0, aq*4 <= 12 < 900
    bReg = *(const float4*)Bbase;                 // brow <= 15 < 900

    for (int k0 = 0; k0 < DIN; k0 += 16) {
        As[(aq * 4 + 0) * 68 + ar] = aReg.x;
        As[(aq * 4 + 1) * 68 + ar] = aReg.y;
        As[(aq * 4 + 2) * 68 + ar] = aReg.z;
        As[(aq * 4 + 3) * 68 + ar] = aReg.w;
        *(float4*)&Bs[brow * 64 + bcol4] = bReg;
        __syncthreads();

        int kn = k0 + 16;
        if (kn < DIN) {
            aReg = make_float4(0.f, 0.f, 0.f, 0.f);
            if (aValid && kn + aq * 4 < DIN) aReg = *(const float4*)(Abase + kn);
            bReg = make_float4(0.f, 0.f, 0.f, 0.f);
            if (kn + brow < DIN) bReg = *(const float4*)(Bbase + (size_t)kn * DM);
        }

#pragma unroll
        for (int kk = 0; kk < 16; kk++) {
            float4 av = *(const float4*)&As[kk * 68 + (ty << 2)];
            float4 bv = *(const float4*)&Bs[kk * 64 + (tx << 2)];
            acc[0][0] += av.x * bv.x; acc[0][1] += av.x * bv.y; acc[0][2] += av.x * bv.z; acc[0][3] += av.x * bv.w;
            acc[1][0] += av.y * bv.x; acc[1][1] += av.y * bv.y; acc[1][2] += av.y * bv.z; acc[1][3] += av.y * bv.w;
            acc[2][0] += av.z * bv.x; acc[2][1] += av.z * bv.y; acc[2][2] += av.z * bv.z; acc[2][3] += av.z * bv.w;
            acc[3][0] += av.w * bv.x; acc[3][1] += av.w * bv.y; acc[3][2] += av.w * bv.z; acc[3][3] += av.w * bv.w;
        }
        __syncthreads();
    }

#pragma unroll
    for (int i = 0; i < 4; i++) {
        int r = (ty << 2) + i;
        if (r < rows) {
            float g = sGate[r];
            float4 o;
            o.x = g * (acc[i][0] + sBias[(tx << 2) + 0]);
            o.y = g * (acc[i][1] + sBias[(tx << 2) + 1]);
            o.z = g * (acc[i][2] + sBias[(tx << 2) + 2]);
            o.w = g * (acc[i][3] + sBias[(tx << 2) + 3]);
            *(float4*)(g_scratch + (size_t)sEntry[r] * DM + n0 + (tx << 2)) = o;
        }
    }
}

// ---------------------------------------------------------------------------
// Combine slot0 + slot1, quantize to bf16 (matching reference astype), write f32.
__global__ void combine_kernel(float* __restrict__ out) {
    int idx = blockIdx.x * blockDim.x + threadIdx.x;   // one float4 of final_out
    int b   = idx >> 7;                                // 128 float4 per row
    int m4  = (idx & 127) << 2;
    float g1 = g_gate[2 * b], g2 = g_gate[2 * b + 1];
    float4 v = make_float4(0.f, 0.f, 0.f, 0.f);
    if (g1 > 0.f) {
        float4 s = *(const float4*)(g_scratch + (size_t)(2 * b) * DM + m4);
        v.x += s.x; v.y += s.y; v.z += s.z; v.w += s.w;
    }
    if (g2 > 0.f) {
        float4 s = *(const float4*)(g_scratch + (size_t)(2 * b + 1) * DM + m4);
        v.x += s.x; v.y += s.y; v.z += s.z; v.w += s.w;
    }
    float4 o;
    o.x = __bfloat162float(__float2bfloat16(v.x));
    o.y = __bfloat162float(__float2bfloat16(v.y));
    o.z = __bfloat162float(__float2bfloat16(v.z));
    o.w = __bfloat162float(__float2bfloat16(v.w));
    ((float4*)out)[idx] = o;
}

// ---------------------------------------------------------------------------
extern "C" void kernel_launch(void* const* d_in, const int* in_sizes, int n_in,
                              void* d_out, int out_size)
{
    const float* X      = (const float*)d_in[0];   // [16384, 900]
    const float* logits = (const float*)d_in[1];   // [16384, 8]
    const int*   masks  = (const int*)  d_in[2];   // [16384, 8]
    const float* selemb = (const float*)d_in[3];   // [16384, 8, 128]
    const float* W      = (const float*)d_in[4];   // [8, 900, 512]
    const float* bias   = (const float*)d_in[5];   // [8, 512]
    float* out = (float*)d_out;

    init_kernel<<<1, 32>>>();
    phaseA_kernel<<<NB / 32, 1024>>>(logits, masks, selemb, out);
    guide_kernel<<<1, 512>>>(out);
    dim3 g(NB / 64, DM / 64, NE);   // 256 row-tiles x 8 col-tiles x 8 experts
    gemm_kernel<<<g, 256>>>(X, W, bias);
    combine_kernel<<<(NB * DM / 4) / 256, 256>>>(out);
}

// round 2
// speedup vs baseline: 1.1920x; 1.1920x over previous
#include <cuda_runtime.h>
#include <cuda_bf16.h>

#define NB   16384
#define NE   8
#define DIN  900
#define DM   512
#define DSEL 128
#define EPSF 1e-9f

#define OUT_GUIDE (NB * DM)        // 8388608
#define OUT_SEL   (NB * DM + 1)    // 8388609

// Scratch: per-(token,slot) expert output (gate-scaled), slot in {0,1}.
__device__ float g_scratch[(size_t)2 * NB * DM];   // 64 MB
__device__ int   g_bucket[NE * NB];                // token*2+slot entries per expert
__device__ int   g_count[NE];
__device__ float g_gate[2 * NB];                   // gate per (token,slot); 0 if unused
__device__ float g_partial[512];                   // guide-loss partial sums

// ---------------------------------------------------------------------------
__global__ void init_kernel() {
    int t = threadIdx.x;
    if (t < NE) g_count[t] = 0;
}

// ---------------------------------------------------------------------------
// Phase A: one warp per row. Softmax, inactive mixture -> selection embedding,
// top-2 gates, guide partials, expert bucketing (block-aggregated atomics).
__global__ void __launch_bounds__(1024) phaseA_kernel(
    const float* __restrict__ logits,
    const int*   __restrict__ masks,
    const float* __restrict__ selemb,
    float*       __restrict__ out)
{
    __shared__ int   lcount[NE];
    __shared__ int   lbase[NE];
    __shared__ int   staging[NE][32];
    __shared__ float warpS[32];

    int tid  = threadIdx.x;
    int warp = tid >> 5;
    int lane = tid & 31;
    if (tid < NE) lcount[tid] = 0;
    __syncthreads();

    int b = blockIdx.x * 32 + warp;

    float raw[NE];
    float mx = -1e30f;
#pragma unroll
    for (int e = 0; e < NE; e++) { raw[e] = logits[b * NE + e]; mx = fmaxf(mx, raw[e]); }
    float sum = 0.f;
#pragma unroll
    for (int e = 0; e < NE; e++) { raw[e] = expf(raw[e] - mx); sum += raw[e]; }
    float inv = 1.f / sum;
    int m[NE];
#pragma unroll
    for (int e = 0; e < NE; e++) { raw[e] *= inv; m[e] = masks[b * NE + e]; }

    // inactive-expert mixture weights
    float w[NE]; float isum = 0.f;
#pragma unroll
    for (int e = 0; e < NE; e++) { w[e] = (m[e] == 1) ? 0.f : raw[e]; isum += w[e]; }
    float winv = 1.f / (isum + EPSF);

    // active gates + guide partial
    float a[NE]; float srow = 0.f;
#pragma unroll
    for (int e = 0; e < NE; e++) {
        w[e] *= winv;
        a[e] = (m[e] == 1) ? raw[e] : 0.f;
        srow += a[e];
    }

    // top-2 (lowest index wins ties, matching jax.lax.top_k)
    float v1 = -1.f, v2 = -1.f; int e1 = 0, e2 = 0;
#pragma unroll
    for (int e = 0; e < NE; e++) {
        if (a[e] > v1) { v2 = v1; e2 = e1; v1 = a[e]; e1 = e; }
        else if (a[e] > v2) { v2 = a[e]; e2 = e; }
    }
    float gs = 1.f / (v1 + v2 + EPSF);
    float g1 = v1 * gs, g2 = v2 * gs;

    // selection embedding: each lane handles 4 consecutive s positions
    const float4* base = (const float4*)(selemb + (size_t)b * NE * DSEL);
    float4 acc = make_float4(0.f, 0.f, 0.f, 0.f);
#pragma unroll
    for (int e = 0; e < NE; e++) {
        float4 v = base[e * (DSEL / 4) + lane];
        acc.x += w[e] * v.x; acc.y += w[e] * v.y;
        acc.z += w[e] * v.z; acc.w += w[e] * v.w;
    }
    // OUT_SEL is an odd float offset -> scalar stores (16B misaligned)
    float* dst = out + OUT_SEL + (size_t)b * DSEL + lane * 4;
    dst[0] = acc.x; dst[1] = acc.y; dst[2] = acc.z; dst[3] = acc.w;

    if (lane == 0) {
        g_gate[2 * b]     = g1;
        g_gate[2 * b + 1] = g2;
        if (g1 > 0.f) { int p = atomicAdd(&lcount[e1], 1); staging[e1][p] = 2 * b; }
        if (g2 > 0.f) { int p = atomicAdd(&lcount[e2], 1); staging[e2][p] = 2 * b + 1; }
        warpS[warp] = srow;
    }
    __syncthreads();
    if (tid < NE) lbase[tid] = atomicAdd(&g_count[tid], lcount[tid]);
    if (tid == 0) {
        float s = 0.f;
        for (int i = 0; i < 32; i++) s += warpS[i];
        g_partial[blockIdx.x] = s;
    }
    __syncthreads();
#pragma unroll
    for (int e = 0; e < NE; e++) {
        for (int i = tid; i < lcount[e]; i += blockDim.x)
            g_bucket[e * NB + lbase[e] + i] = staging[e][i];
    }
}

// ---------------------------------------------------------------------------
__global__ void guide_kernel(float* __restrict__ out) {
    __shared__ float sm[512];
    int t = threadIdx.x;
    sm[t] = g_partial[t];
    __syncthreads();
    for (int s = 256; s > 0; s >>= 1) {
        if (t < s) sm[t] += sm[t + s];
        __syncthreads();
    }
    if (t == 0) {
        float sv = sm[0] / (float)NB;
        float d = 1.f - sv;
        out[OUT_GUIDE] = d * d;
    }
}

// ---------------------------------------------------------------------------
// Grouped SGEMM: 128x128 block tile, BK=8, 256 threads, 8x8 micro-tile,
// double-buffered smem with register-staged global loads.
// Inner loop: 4 LDS.128 per 64 FFMA (vs 2:16 before) -> fma-pipe bound.
#define BK 8
#define ASTRIDE 132   // padded so transpose STS pairs hit different banks

__global__ void __launch_bounds__(256, 2) gemm_kernel(
    const float* __restrict__ X,
    const float* __restrict__ W,
    const float* __restrict__ bias)
{
    int e   = blockIdx.z;
    int cnt = g_count[e];
    int rt0 = blockIdx.x * 128;
    if (rt0 >= cnt) return;
    int rows = cnt - rt0; if (rows > 128) rows = 128;
    int n0 = blockIdx.y * 128;

    __shared__ float As[2][BK * ASTRIDE];  // [k][m]
    __shared__ float Bs[2][BK * 128];      // [k][n]
    __shared__ int   sEntry[128];
    __shared__ float sGate[128];
    __shared__ float sBias[128];

    int t = threadIdx.x;
    if (t < 128) {
        int entry = 0; float g = 0.f;
        if (t < rows) { entry = g_bucket[e * NB + rt0 + t]; g = g_gate[entry]; }
        sEntry[t] = entry;
        sGate[t]  = g;
        sBias[t]  = bias[e * DM + n0 + t];
    }
    __syncthreads();

    // A loader: 256 threads -> 128 rows x 2 float4 along k
    int ar = t >> 1, aq = t & 1;
    bool aValid = (ar < rows);
    const float* Abase = X + (size_t)(sEntry[ar] >> 1) * DIN + aq * 4;
    // B loader: 256 threads -> 8 k-rows x 32 float4 along n
    int brow = t >> 5, bcol = (t & 31) << 2;
    const float* Bbase = W + (size_t)e * DIN * DM + (size_t)brow * DM + n0 + bcol;

    int tx = t & 15, ty = t >> 4;          // 16x16 thread grid
    int mA = ty << 2;                      // rows mA..mA+3 and 64+mA..64+mA+3
    int nB = tx << 2;                      // cols nB..nB+3 and 64+nB..64+nB+3

    float acc[8][8];
#pragma unroll
    for (int i = 0; i < 8; i++)
#pragma unroll
        for (int j = 0; j < 8; j++) acc[i][j] = 0.f;

    // prologue: load k-tile 0
    float4 aReg = make_float4(0.f, 0.f, 0.f, 0.f);
    float4 bReg = make_float4(0.f, 0.f, 0.f, 0.f);
    if (aValid) aReg = *(const float4*)Abase;
    bReg = *(const float4*)Bbase;

    int buf = 0;
    {
        As[0][(aq * 4 + 0) * ASTRIDE + ar] = aReg.x;
        As[0][(aq * 4 + 1) * ASTRIDE + ar] = aReg.y;
        As[0][(aq * 4 + 2) * ASTRIDE + ar] = aReg.z;
        As[0][(aq * 4 + 3) * ASTRIDE + ar] = aReg.w;
        *(float4*)&Bs[0][brow * 128 + bcol] = bReg;
        __syncthreads();
    }

    for (int k0 = 0; k0 < DIN; k0 += BK) {
        int kn = k0 + BK;
        bool more = (kn < DIN);
        if (more) {
            aReg = make_float4(0.f, 0.f, 0.f, 0.f);
            if (aValid && (kn + aq * 4 + 4 <= DIN)) aReg = *(const float4*)(Abase + kn);
            bReg = make_float4(0.f, 0.f, 0.f, 0.f);
            if (kn + brow < DIN) bReg = *(const float4*)(Bbase + (size_t)kn * DM);
        }

        const float* __restrict__ Ab = As[buf];
        const float* __restrict__ Bb = Bs[buf];
#pragma unroll
        for (int kk = 0; kk < BK; kk++) {
            float4 a0 = *(const float4*)&Ab[kk * ASTRIDE + mA];
            float4 a1 = *(const float4*)&Ab[kk * ASTRIDE + 64 + mA];
            float4 b0 = *(const float4*)&Bb[kk * 128 + nB];
            float4 b1 = *(const float4*)&Bb[kk * 128 + 64 + nB];
            float av[8] = {a0.x, a0.y, a0.z, a0.w, a1.x, a1.y, a1.z, a1.w};
            float bv[8] = {b0.x, b0.y, b0.z, b0.w, b1.x, b1.y, b1.z, b1.w};
#pragma unroll
            for (int i = 0; i < 8; i++)
#pragma unroll
                for (int j = 0; j < 8; j++)
                    acc[i][j] += av[i] * bv[j];
        }

        if (more) {
            int nb = buf ^ 1;
            As[nb][(aq * 4 + 0) * ASTRIDE + ar] = aReg.x;
            As[nb][(aq * 4 + 1) * ASTRIDE + ar] = aReg.y;
            As[nb][(aq * 4 + 2) * ASTRIDE + ar] = aReg.z;
            As[nb][(aq * 4 + 3) * ASTRIDE + ar] = aReg.w;
            *(float4*)&Bs[nb][brow * 128 + bcol] = bReg;
            __syncthreads();
            buf = nb;
        }
    }

    // epilogue: bias + gate, write gate-scaled expert output to scratch
#pragma unroll
    for (int i = 0; i < 8; i++) {
        int r = (i < 4) ? (mA + i) : (64 + mA + i - 4);
        if (r < rows) {
            float g = sGate[r];
            float* dst = g_scratch + (size_t)sEntry[r] * DM + n0;
            float4 o0, o1;
            o0.x = g * (acc[i][0] + sBias[nB + 0]);
            o0.y = g * (acc[i][1] + sBias[nB + 1]);
            o0.z = g * (acc[i][2] + sBias[nB + 2]);
            o0.w = g * (acc[i][3] + sBias[nB + 3]);
            o1.x = g * (acc[i][4] + sBias[64 + nB + 0]);
            o1.y = g * (acc[i][5] + sBias[64 + nB + 1]);
            o1.z = g * (acc[i][6] + sBias[64 + nB + 2]);
            o1.w = g * (acc[i][7] + sBias[64 + nB + 3]);
            *(float4*)(dst + nB) = o0;
            *(float4*)(dst + 64 + nB) = o1;
        }
    }
}

// ---------------------------------------------------------------------------
// Combine slot0 + slot1, quantize to bf16 (matching reference astype), write f32.
__global__ void combine_kernel(float* __restrict__ out) {
    int idx = blockIdx.x * blockDim.x + threadIdx.x;   // one float4 of final_out
    int b   = idx >> 7;                                // 128 float4 per row
    int m4  = (idx & 127) << 2;
    float g1 = g_gate[2 * b], g2 = g_gate[2 * b + 1];
    float4 v = make_float4(0.f, 0.f, 0.f, 0.f);
    if (g1 > 0.f) {
        float4 s = *(const float4*)(g_scratch + (size_t)(2 * b) * DM + m4);
        v.x += s.x; v.y += s.y; v.z += s.z; v.w += s.w;
    }
    if (g2 > 0.f) {
        float4 s = *(const float4*)(g_scratch + (size_t)(2 * b + 1) * DM + m4);
        v.x += s.x; v.y += s.y; v.z += s.z; v.w += s.w;
    }
    float4 o;
    o.x = __bfloat162float(__float2bfloat16(v.x));
    o.y = __bfloat162float(__float2bfloat16(v.y));
    o.z = __bfloat162float(__float2bfloat16(v.z));
    o.w = __bfloat162float(__float2bfloat16(v.w));
    ((float4*)out)[idx] = o;
}

// ---------------------------------------------------------------------------
extern "C" void kernel_launch(void* const* d_in, const int* in_sizes, int n_in,
                              void* d_out, int out_size)
{
    const float* X      = (const float*)d_in[0];   // [16384, 900]
    const float* logits = (const float*)d_in[1];   // [16384, 8]
    const int*   masks  = (const int*)  d_in[2];   // [16384, 8]
    const float* selemb = (const float*)d_in[3];   // [16384, 8, 128]
    const float* W      = (const float*)d_in[4];   // [8, 900, 512]
    const float* bias   = (const float*)d_in[5];   // [8, 512]
    float* out = (float*)d_out;

    init_kernel<<<1, 32>>>();
    phaseA_kernel<<<NB / 32, 1024>>>(logits, masks, selemb, out);
    guide_kernel<<<1, 512>>>(out);
    dim3 g(NB / 128, DM / 128, NE);   // 128 row-tiles x 4 col-tiles x 8 experts
    gemm_kernel<<<g, 256>>>(X, W, bias);
    combine_kernel<<<(NB * DM / 4) / 256, 256>>>(out);
}

// round 4
// speedup vs baseline: 1.7476x; 1.4662x over previous
#include <cuda_runtime.h>
#include <cuda_bf16.h>
#include <cstdint>

#define NB   16384
#define NE   8
#define DIN  900
#define DM   512
#define DSEL 128
#define EPSF 1e-9f

#define KP     912            // 57 * 16, zero-padded K
#define NK16   57
#define NSTG   5              // cp.async pipeline depth
#define STAGE  24576          // bytes per stage: 4 arrays * 128 rows * 48B
#define AHI    0
#define ALO    6144
#define BHI    12288
#define BLO    18432
#define DYNSM  (NSTG * STAGE) // 122880

#define OUT_GUIDE (NB * DM)
#define OUT_SEL   (NB * DM + 1)

__device__ float g_scratch[(size_t)2 * NB * DM];     // gated per-(token,slot) outputs
__device__ int   g_bucket[NE * NB];
__device__ int   g_count[NE];
__device__ float g_gate[2 * NB];
__device__ float g_partial[512];
__device__ __nv_bfloat16 g_Xhi[(size_t)NB * KP];
__device__ __nv_bfloat16 g_Xlo[(size_t)NB * KP];
__device__ __nv_bfloat16 g_Whi[(size_t)NE * DM * KP];   // W transposed [e][n][k]
__device__ __nv_bfloat16 g_Wlo[(size_t)NE * DM * KP];

// ---------------------------------------------------------------------------
__device__ __forceinline__ uint32_t smem_u32(const void* p) {
    return (uint32_t)__cvta_generic_to_shared(p);
}
__device__ __forceinline__ void cp16(uint32_t s, const void* g) {
    asm volatile("cp.async.cg.shared.global [%0], [%1], 16;" :: "r"(s), "l"(g));
}
__device__ __forceinline__ void cp_commit() {
    asm volatile("cp.async.commit_group;" ::: "memory");
}
template <int N>
__device__ __forceinline__ void cp_wait() {
    asm volatile("cp.async.wait_group %0;" :: "n"(N) : "memory");
}
__device__ __forceinline__ void ldm_x4(uint32_t* r, uint32_t a) {
    asm volatile("ldmatrix.sync.aligned.m8n8.x4.shared.b16 {%0,%1,%2,%3}, [%4];"
                 : "=r"(r[0]), "=r"(r[1]), "=r"(r[2]), "=r"(r[3]) : "r"(a));
}
__device__ __forceinline__ void ldm_x2(uint32_t* r, uint32_t a) {
    asm volatile("ldmatrix.sync.aligned.m8n8.x2.shared.b16 {%0,%1}, [%2];"
                 : "=r"(r[0]), "=r"(r[1]) : "r"(a));
}
#define MMA_BF16(acc, a, b) \
    asm volatile("mma.sync.aligned.m16n8k16.row.col.f32.bf16.bf16.f32 " \
        "{%0,%1,%2,%3}, {%4,%5,%6,%7}, {%8,%9}, {%0,%1,%2,%3};" \
        : "+f"((acc)[0]), "+f"((acc)[1]), "+f"((acc)[2]), "+f"((acc)[3]) \
        : "r"((a)[0]), "r"((a)[1]), "r"((a)[2]), "r"((a)[3]), \
          "r"((b)[0]), "r"((b)[1]))

// ---------------------------------------------------------------------------
__global__ void init_kernel() {
    int t = threadIdx.x;
    if (t < NE) g_count[t] = 0;
}

// ---------------------------------------------------------------------------
// Split X into bf16 hi/lo, pad K to 912 with zeros.
__global__ void split_x_kernel(const float* __restrict__ X) {
    size_t i = (size_t)blockIdx.x * blockDim.x + threadIdx.x;
    if (i >= (size_t)NB * KP) return;
    int b = (int)(i / KP), k = (int)(i % KP);
    float v = (k < DIN) ? X[(size_t)b * DIN + k] : 0.f;
    __nv_bfloat16 h = __float2bfloat16(v);
    g_Xhi[i] = h;
    g_Xlo[i] = __float2bfloat16(v - __bfloat162float(h));
}

// ---------------------------------------------------------------------------
// Transpose + split W[e][k][n] -> [e][n][kpad] bf16 hi/lo.
__global__ void split_w_kernel(const float* __restrict__ W) {
    __shared__ float tile[32][33];
    int e = blockIdx.z;
    int k0 = blockIdx.x * 32;
    int n0 = blockIdx.y * 32;
    int tx = threadIdx.x, ty = threadIdx.y;
#pragma unroll
    for (int i = 0; i < 4; i++) {
        int k = k0 + ty + i * 8;
        tile[ty + i * 8][tx] = (k < DIN) ? W[((size_t)e * DIN + k) * DM + n0 + tx] : 0.f;
    }
    __syncthreads();
#pragma unroll
    for (int i = 0; i < 4; i++) {
        int n = n0 + ty + i * 8;
        int kk = k0 + tx;
        if (kk < KP) {
            float v = tile[tx][ty + i * 8];
            __nv_bfloat16 h = __float2bfloat16(v);
            size_t idx = ((size_t)e * DM + n) * KP + kk;
            g_Whi[idx] = h;
            g_Wlo[idx] = __float2bfloat16(v - __bfloat162float(h));
        }
    }
}

// ---------------------------------------------------------------------------
// Phase A (unchanged, proven): softmax, inactive mixture, top-2, bucketing.
__global__ void __launch_bounds__(1024) phaseA_kernel(
    const float* __restrict__ logits,
    const int*   __restrict__ masks,
    const float* __restrict__ selemb,
    float*       __restrict__ out)
{
    __shared__ int   lcount[NE];
    __shared__ int   lbase[NE];
    __shared__ int   staging[NE][32];
    __shared__ float warpS[32];

    int tid  = threadIdx.x;
    int warp = tid >> 5;
    int lane = tid & 31;
    if (tid < NE) lcount[tid] = 0;
    __syncthreads();

    int b = blockIdx.x * 32 + warp;

    float raw[NE];
    float mx = -1e30f;
#pragma unroll
    for (int e = 0; e < NE; e++) { raw[e] = logits[b * NE + e]; mx = fmaxf(mx, raw[e]); }
    float sum = 0.f;
#pragma unroll
    for (int e = 0; e < NE; e++) { raw[e] = expf(raw[e] - mx); sum += raw[e]; }
    float inv = 1.f / sum;
    int m[NE];
#pragma unroll
    for (int e = 0; e < NE; e++) { raw[e] *= inv; m[e] = masks[b * NE + e]; }

    float w[NE]; float isum = 0.f;
#pragma unroll
    for (int e = 0; e < NE; e++) { w[e] = (m[e] == 1) ? 0.f : raw[e]; isum += w[e]; }
    float winv = 1.f / (isum + EPSF);

    float a[NE]; float srow = 0.f;
#pragma unroll
    for (int e = 0; e < NE; e++) {
        w[e] *= winv;
        a[e] = (m[e] == 1) ? raw[e] : 0.f;
        srow += a[e];
    }

    float v1 = -1.f, v2 = -1.f; int e1 = 0, e2 = 0;
#pragma unroll
    for (int e = 0; e < NE; e++) {
        if (a[e] > v1) { v2 = v1; e2 = e1; v1 = a[e]; e1 = e; }
        else if (a[e] > v2) { v2 = a[e]; e2 = e; }
    }
    float gs = 1.f / (v1 + v2 + EPSF);
    float g1 = v1 * gs, g2 = v2 * gs;

    const float4* base = (const float4*)(selemb + (size_t)b * NE * DSEL);
    float4 acc = make_float4(0.f, 0.f, 0.f, 0.f);
#pragma unroll
    for (int e = 0; e < NE; e++) {
        float4 v = base[e * (DSEL / 4) + lane];
        acc.x += w[e] * v.x; acc.y += w[e] * v.y;
        acc.z += w[e] * v.z; acc.w += w[e] * v.w;
    }
    float* dst = out + OUT_SEL + (size_t)b * DSEL + lane * 4;
    dst[0] = acc.x; dst[1] = acc.y; dst[2] = acc.z; dst[3] = acc.w;

    if (lane == 0) {
        g_gate[2 * b]     = g1;
        g_gate[2 * b + 1] = g2;
        if (g1 > 0.f) { int p = atomicAdd(&lcount[e1], 1); staging[e1][p] = 2 * b; }
        if (g2 > 0.f) { int p = atomicAdd(&lcount[e2], 1); staging[e2][p] = 2 * b + 1; }
        warpS[warp] = srow;
    }
    __syncthreads();
    if (tid < NE) lbase[tid] = atomicAdd(&g_count[tid], lcount[tid]);
    if (tid == 0) {
        float s = 0.f;
        for (int i = 0; i < 32; i++) s += warpS[i];
        g_partial[blockIdx.x] = s;
    }
    __syncthreads();
#pragma unroll
    for (int e = 0; e < NE; e++) {
        for (int i = tid; i < lcount[e]; i += blockDim.x)
            g_bucket[e * NB + lbase[e] + i] = staging[e][i];
    }
}

// ---------------------------------------------------------------------------
__global__ void guide_kernel(float* __restrict__ out) {
    __shared__ float sm[512];
    int t = threadIdx.x;
    sm[t] = g_partial[t];
    __syncthreads();
    for (int s = 256; s > 0; s >>= 1) {
        if (t < s) sm[t] += sm[t + s];
        __syncthreads();
    }
    if (t == 0) {
        float sv = sm[0] / (float)NB;
        float d = 1.f - sv;
        out[OUT_GUIDE] = d * d;
    }
}

// ---------------------------------------------------------------------------
// Tensor-core grouped GEMM: mma.sync bf16, 3-pass hi/lo split.
// CTA tile 128x128, BK=16, 5-stage cp.async pipeline, 8 warps (2m x 4n).
extern __shared__ char sm_dyn[];

__global__ void __launch_bounds__(256, 1) gemm_kernel(
    const float* __restrict__ bias)
{
    int e   = blockIdx.z;
    int cnt = g_count[e];
    int rt0 = blockIdx.x * 128;
    if (rt0 >= cnt) return;
    int rows = cnt - rt0; if (rows > 128) rows = 128;
    int n0 = blockIdx.y * 128;

    __shared__ int   sEntry[128];
    __shared__ float sGate[128];
    __shared__ float sBias[128];

    int t = threadIdx.x;
    int wid = t >> 5, lane = t & 31;
    int wm = wid & 1, wn = wid >> 1;       // 2 x 4 warp grid

    if (t < 128) {
        int entry = 0; float g = 0.f;
        if (t < rows) { entry = g_bucket[e * NB + rt0 + t]; g = g_gate[entry]; }
        sEntry[t] = entry; sGate[t] = g;
        sBias[t]  = bias[e * DM + n0 + t];
    }
    __syncthreads();

    uint32_t dynb = smem_u32(sm_dyn);

    // per-thread cp.async sources: row = t>>1, chunk = t&1 (16B each)
    int lrow = t >> 1, lch = t & 1;
    const __nv_bfloat16* aHiSrc =
        g_Xhi + (size_t)(sEntry[lrow] >> 1) * KP + lch * 8;
    const __nv_bfloat16* aLoSrc =
        g_Xlo + (size_t)(sEntry[lrow] >> 1) * KP + lch * 8;
    const __nv_bfloat16* bHiSrc =
        g_Whi + ((size_t)e * DM + n0 + lrow) * KP + lch * 8;
    const __nv_bfloat16* bLoSrc =
        g_Wlo + ((size_t)e * DM + n0 + lrow) * KP + lch * 8;
    uint32_t smoff = lrow * 48 + lch * 16;

    // prologue: stages 0..3
#pragma unroll
    for (int s = 0; s < NSTG - 1; s++) {
        uint32_t sb = dynb + s * STAGE;
        cp16(sb + AHI + smoff, aHiSrc + s * 16);
        cp16(sb + ALO + smoff, aLoSrc + s * 16);
        cp16(sb + BHI + smoff, bHiSrc + s * 16);
        cp16(sb + BLO + smoff, bLoSrc + s * 16);
        cp_commit();
    }

    float acc[4][4][4];
#pragma unroll
    for (int i = 0; i < 4; i++)
#pragma unroll
        for (int j = 0; j < 4; j++)
#pragma unroll
            for (int q = 0; q < 4; q++) acc[i][j][q] = 0.f;

    // fragment address offsets
    int l7 = lane & 7;
    uint32_t aRowOff = (uint32_t)((wm * 64 + l7 + ((lane >> 3) & 1) * 8) * 48
                                  + ((lane >> 4) & 1) * 16);
    int bl = lane & 15;
    uint32_t bRowOff = (uint32_t)((wn * 32 + (bl & 7)) * 48 + ((bl >> 3) & 1) * 16);

    for (int ks = 0; ks < NK16; ks++) {
        cp_wait<NSTG - 2>();
        __syncthreads();

        uint32_t sb = dynb + (ks % NSTG) * STAGE;

        uint32_t bh[4][2], blo[4][2];
#pragma unroll
        for (int tn = 0; tn < 4; tn++) {
            uint32_t ba = sb + BHI + bRowOff + tn * 8 * 48;
            ldm_x2(bh[tn], ba);
            ldm_x2(blo[tn], ba + (BLO - BHI));
        }
#pragma unroll
        for (int tm = 0; tm < 4; tm++) {
            uint32_t aa = sb + AHI + aRowOff + tm * 16 * 48;
            uint32_t ah[4], al[4];
            ldm_x4(ah, aa);
            ldm_x4(al, aa + (ALO - AHI));
#pragma unroll
            for (int tn = 0; tn < 4; tn++) {
                MMA_BF16(acc[tm][tn], ah, bh[tn]);
                MMA_BF16(acc[tm][tn], ah, blo[tn]);
                MMA_BF16(acc[tm][tn], al, bh[tn]);
            }
        }
        __syncthreads();

        int ns = ks + NSTG - 1;
        if (ns < NK16) {
            uint32_t nb = dynb + (ns % NSTG) * STAGE;
            cp16(nb + AHI + smoff, aHiSrc + ns * 16);
            cp16(nb + ALO + smoff, aLoSrc + ns * 16);
            cp16(nb + BHI + smoff, bHiSrc + ns * 16);
            cp16(nb + BLO + smoff, bLoSrc + ns * 16);
        }
        cp_commit();
    }

    // epilogue: bias + gate, write to scratch
    int rq = lane >> 2, cq = (lane & 3) * 2;
#pragma unroll
    for (int tm = 0; tm < 4; tm++) {
        int r0 = wm * 64 + tm * 16 + rq;
        int r1 = r0 + 8;
#pragma unroll
        for (int tn = 0; tn < 4; tn++) {
            int cl = wn * 32 + tn * 8 + cq;
            float b0 = sBias[cl], b1 = sBias[cl + 1];
            if (r0 < rows) {
                float g = sGate[r0];
                float2 o = make_float2(g * (acc[tm][tn][0] + b0),
                                       g * (acc[tm][tn][1] + b1));
                *(float2*)(g_scratch + (size_t)sEntry[r0] * DM + n0 + cl) = o;
            }
            if (r1 < rows) {
                float g = sGate[r1];
                float2 o = make_float2(g * (acc[tm][tn][2] + b0),
                                       g * (acc[tm][tn][3] + b1));
                *(float2*)(g_scratch + (size_t)sEntry[r1] * DM + n0 + cl) = o;
            }
        }
    }
}

// ---------------------------------------------------------------------------
__global__ void combine_kernel(float* __restrict__ out) {
    int idx = blockIdx.x * blockDim.x + threadIdx.x;
    int b   = idx >> 7;
    int m4  = (idx & 127) << 2;
    float g1 = g_gate[2 * b], g2 = g_gate[2 * b + 1];
    float4 v = make_float4(0.f, 0.f, 0.f, 0.f);
    if (g1 > 0.f) {
        float4 s = *(const float4*)(g_scratch + (size_t)(2 * b) * DM + m4);
        v.x += s.x; v.y += s.y; v.z += s.z; v.w += s.w;
    }
    if (g2 > 0.f) {
        float4 s = *(const float4*)(g_scratch + (size_t)(2 * b + 1) * DM + m4);
        v.x += s.x; v.y += s.y; v.z += s.z; v.w += s.w;
    }
    float4 o;
    o.x = __bfloat162float(__float2bfloat16(v.x));
    o.y = __bfloat162float(__float2bfloat16(v.y));
    o.z = __bfloat162float(__float2bfloat16(v.z));
    o.w = __bfloat162float(__float2bfloat16(v.w));
    ((float4*)out)[idx] = o;
}

// ---------------------------------------------------------------------------
extern "C" void kernel_launch(void* const* d_in, const int* in_sizes, int n_in,
                              void* d_out, int out_size)
{
    const float* X      = (const float*)d_in[0];
    const float* logits = (const float*)d_in[1];
    const int*   masks  = (const int*)  d_in[2];
    const float* selemb = (const float*)d_in[3];
    const float* W      = (const float*)d_in[4];
    const float* bias   = (const float*)d_in[5];
    float* out = (float*)d_out;

    cudaFuncSetAttribute(gemm_kernel,
                         cudaFuncAttributeMaxDynamicSharedMemorySize, DYNSM);

    init_kernel<<<1, 32>>>();
    split_x_kernel<<<(int)(((size_t)NB * KP + 255) / 256), 256>>>(X);
    dim3 wg((KP + 31) / 32, DM / 32, NE);
    split_w_kernel<<<wg, dim3(32, 8)>>>(W);
    phaseA_kernel<<<NB / 32, 1024>>>(logits, masks, selemb, out);
    guide_kernel<<<1, 512>>>(out);
    dim3 g(NB / 128, DM / 128, NE);
    gemm_kernel<<<g, 256, DYNSM>>>(bias);
    combine_kernel<<<(NB * DM / 4) / 256, 256>>>(out);
}

// round 5
// speedup vs baseline: 2.1415x; 1.2254x over previous
#include <cuda_runtime.h>
#include <cuda_bf16.h>
#include <cstdint>

#define NB   16384
#define NE   8
#define DIN  900
#define DM   512
#define DSEL 128
#define EPSF 1e-9f

#define KP     912            // 57 * 16, zero-padded K
#define NK16   57
#define NSTG   3              // cp.async pipeline depth
#define STAGE  24576          // bytes per stage: 4 arrays * 128 rows * 48B
#define AHI    0
#define ALO    6144
#define BHI    12288
#define BLO    18432
#define DYNSM  (NSTG * STAGE) // 73728

#define OUT_GUIDE (NB * DM)
#define OUT_SEL   (NB * DM + 1)

__device__ float g_scratch[(size_t)2 * NB * DM];     // gated per-(token,slot) outputs
__device__ int   g_bucket[NE * NB];
__device__ int   g_count[NE];
__device__ float g_gate[2 * NB];
__device__ float g_partial[512];
__device__ __nv_bfloat16 g_Xhi[(size_t)NB * KP];
__device__ __nv_bfloat16 g_Xlo[(size_t)NB * KP];
__device__ __nv_bfloat16 g_Whi[(size_t)NE * DM * KP];   // W transposed [e][n][k]
__device__ __nv_bfloat16 g_Wlo[(size_t)NE * DM * KP];

// ---------------------------------------------------------------------------
__device__ __forceinline__ uint32_t smem_u32(const void* p) {
    return (uint32_t)__cvta_generic_to_shared(p);
}
__device__ __forceinline__ void cp16(uint32_t s, const void* g) {
    asm volatile("cp.async.cg.shared.global [%0], [%1], 16;" :: "r"(s), "l"(g));
}
__device__ __forceinline__ void cp_commit() {
    asm volatile("cp.async.commit_group;" ::: "memory");
}
template <int N>
__device__ __forceinline__ void cp_wait() {
    asm volatile("cp.async.wait_group %0;" :: "n"(N) : "memory");
}
__device__ __forceinline__ void ldm_x4(uint32_t* r, uint32_t a) {
    asm volatile("ldmatrix.sync.aligned.m8n8.x4.shared.b16 {%0,%1,%2,%3}, [%4];"
                 : "=r"(r[0]), "=r"(r[1]), "=r"(r[2]), "=r"(r[3]) : "r"(a));
}
__device__ __forceinline__ void ldm_x2(uint32_t* r, uint32_t a) {
    asm volatile("ldmatrix.sync.aligned.m8n8.x2.shared.b16 {%0,%1}, [%2];"
                 : "=r"(r[0]), "=r"(r[1]) : "r"(a));
}
#define MMA_BF16(acc, a, b) \
    asm volatile("mma.sync.aligned.m16n8k16.row.col.f32.bf16.bf16.f32 " \
        "{%0,%1,%2,%3}, {%4,%5,%6,%7}, {%8,%9}, {%0,%1,%2,%3};" \
        : "+f"((acc)[0]), "+f"((acc)[1]), "+f"((acc)[2]), "+f"((acc)[3]) \
        : "r"((a)[0]), "r"((a)[1]), "r"((a)[2]), "r"((a)[3]), \
          "r"((b)[0]), "r"((b)[1]))

// ---------------------------------------------------------------------------
__global__ void init_kernel() {
    int t = threadIdx.x;
    if (t < NE) g_count[t] = 0;
}

// ---------------------------------------------------------------------------
// Split X into bf16 hi/lo, pad K to 912 with zeros.
__global__ void split_x_kernel(const float* __restrict__ X) {
    size_t i = (size_t)blockIdx.x * blockDim.x + threadIdx.x;
    if (i >= (size_t)NB * KP) return;
    int b = (int)(i / KP), k = (int)(i % KP);
    float v = (k < DIN) ? X[(size_t)b * DIN + k] : 0.f;
    __nv_bfloat16 h = __float2bfloat16(v);
    g_Xhi[i] = h;
    g_Xlo[i] = __float2bfloat16(v - __bfloat162float(h));
}

// ---------------------------------------------------------------------------
// Transpose + split W[e][k][n] -> [e][n][kpad] bf16 hi/lo.
__global__ void split_w_kernel(const float* __restrict__ W) {
    __shared__ float tile[32][33];
    int e = blockIdx.z;
    int k0 = blockIdx.x * 32;
    int n0 = blockIdx.y * 32;
    int tx = threadIdx.x, ty = threadIdx.y;
#pragma unroll
    for (int i = 0; i < 4; i++) {
        int k = k0 + ty + i * 8;
        tile[ty + i * 8][tx] = (k < DIN) ? W[((size_t)e * DIN + k) * DM + n0 + tx] : 0.f;
    }
    __syncthreads();
#pragma unroll
    for (int i = 0; i < 4; i++) {
        int n = n0 + ty + i * 8;
        int kk = k0 + tx;
        if (kk < KP) {
            float v = tile[tx][ty + i * 8];
            __nv_bfloat16 h = __float2bfloat16(v);
            size_t idx = ((size_t)e * DM + n) * KP + kk;
            g_Whi[idx] = h;
            g_Wlo[idx] = __float2bfloat16(v - __bfloat162float(h));
        }
    }
}

// ---------------------------------------------------------------------------
// Phase A (unchanged, proven): softmax, inactive mixture, top-2, bucketing.
__global__ void __launch_bounds__(1024) phaseA_kernel(
    const float* __restrict__ logits,
    const int*   __restrict__ masks,
    const float* __restrict__ selemb,
    float*       __restrict__ out)
{
    __shared__ int   lcount[NE];
    __shared__ int   lbase[NE];
    __shared__ int   staging[NE][32];
    __shared__ float warpS[32];

    int tid  = threadIdx.x;
    int warp = tid >> 5;
    int lane = tid & 31;
    if (tid < NE) lcount[tid] = 0;
    __syncthreads();

    int b = blockIdx.x * 32 + warp;

    float raw[NE];
    float mx = -1e30f;
#pragma unroll
    for (int e = 0; e < NE; e++) { raw[e] = logits[b * NE + e]; mx = fmaxf(mx, raw[e]); }
    float sum = 0.f;
#pragma unroll
    for (int e = 0; e < NE; e++) { raw[e] = expf(raw[e] - mx); sum += raw[e]; }
    float inv = 1.f / sum;
    int m[NE];
#pragma unroll
    for (int e = 0; e < NE; e++) { raw[e] *= inv; m[e] = masks[b * NE + e]; }

    float w[NE]; float isum = 0.f;
#pragma unroll
    for (int e = 0; e < NE; e++) { w[e] = (m[e] == 1) ? 0.f : raw[e]; isum += w[e]; }
    float winv = 1.f / (isum + EPSF);

    float a[NE]; float srow = 0.f;
#pragma unroll
    for (int e = 0; e < NE; e++) {
        w[e] *= winv;
        a[e] = (m[e] == 1) ? raw[e] : 0.f;
        srow += a[e];
    }

    float v1 = -1.f, v2 = -1.f; int e1 = 0, e2 = 0;
#pragma unroll
    for (int e = 0; e < NE; e++) {
        if (a[e] > v1) { v2 = v1; e2 = e1; v1 = a[e]; e1 = e; }
        else if (a[e] > v2) { v2 = a[e]; e2 = e; }
    }
    float gs = 1.f / (v1 + v2 + EPSF);
    float g1 = v1 * gs, g2 = v2 * gs;

    const float4* base = (const float4*)(selemb + (size_t)b * NE * DSEL);
    float4 acc = make_float4(0.f, 0.f, 0.f, 0.f);
#pragma unroll
    for (int e = 0; e < NE; e++) {
        float4 v = base[e * (DSEL / 4) + lane];
        acc.x += w[e] * v.x; acc.y += w[e] * v.y;
        acc.z += w[e] * v.z; acc.w += w[e] * v.w;
    }
    float* dst = out + OUT_SEL + (size_t)b * DSEL + lane * 4;
    dst[0] = acc.x; dst[1] = acc.y; dst[2] = acc.z; dst[3] = acc.w;

    if (lane == 0) {
        g_gate[2 * b]     = g1;
        g_gate[2 * b + 1] = g2;
        if (g1 > 0.f) { int p = atomicAdd(&lcount[e1], 1); staging[e1][p] = 2 * b; }
        if (g2 > 0.f) { int p = atomicAdd(&lcount[e2], 1); staging[e2][p] = 2 * b + 1; }
        warpS[warp] = srow;
    }
    __syncthreads();
    if (tid < NE) lbase[tid] = atomicAdd(&g_count[tid], lcount[tid]);
    if (tid == 0) {
        float s = 0.f;
        for (int i = 0; i < 32; i++) s += warpS[i];
        g_partial[blockIdx.x] = s;
    }
    __syncthreads();
#pragma unroll
    for (int e = 0; e < NE; e++) {
        for (int i = tid; i < lcount[e]; i += blockDim.x)
            g_bucket[e * NB + lbase[e] + i] = staging[e][i];
    }
}

// ---------------------------------------------------------------------------
__global__ void guide_kernel(float* __restrict__ out) {
    __shared__ float sm[512];
    int t = threadIdx.x;
    sm[t] = g_partial[t];
    __syncthreads();
    for (int s = 256; s > 0; s >>= 1) {
        if (t < s) sm[t] += sm[t + s];
        __syncthreads();
    }
    if (t == 0) {
        float sv = sm[0] / (float)NB;
        float d = 1.f - sv;
        out[OUT_GUIDE] = d * d;
    }
}

// ---------------------------------------------------------------------------
// Tensor-core grouped GEMM: mma.sync bf16, 3-pass hi/lo split.
// CTA tile 128x128, BK=16, 3-stage cp.async pipeline, 8 warps (2m x 4n),
// 2 CTAs/SM, ONE __syncthreads per k-step.
extern __shared__ char sm_dyn[];

__global__ void __launch_bounds__(256, 2) gemm_kernel(
    const float* __restrict__ bias)
{
    int e   = blockIdx.z;
    int cnt = g_count[e];
    int rt0 = blockIdx.x * 128;
    if (rt0 >= cnt) return;
    int rows = cnt - rt0; if (rows > 128) rows = 128;
    int n0 = blockIdx.y * 128;

    __shared__ int   sEntry[128];
    __shared__ float sGate[128];
    __shared__ float sBias[128];

    int t = threadIdx.x;
    int wid = t >> 5, lane = t & 31;
    int wm = wid & 1, wn = wid >> 1;       // 2 x 4 warp grid

    if (t < 128) {
        int entry = 0; float g = 0.f;
        if (t < rows) { entry = g_bucket[e * NB + rt0 + t]; g = g_gate[entry]; }
        sEntry[t] = entry; sGate[t] = g;
        sBias[t]  = bias[e * DM + n0 + t];
    }
    __syncthreads();

    uint32_t dynb = smem_u32(sm_dyn);

    // per-thread cp.async sources: row = t>>1, chunk = t&1 (16B each)
    int lrow = t >> 1, lch = t & 1;
    const __nv_bfloat16* aHiSrc =
        g_Xhi + (size_t)(sEntry[lrow] >> 1) * KP + lch * 8;
    const __nv_bfloat16* aLoSrc =
        g_Xlo + (size_t)(sEntry[lrow] >> 1) * KP + lch * 8;
    const __nv_bfloat16* bHiSrc =
        g_Whi + ((size_t)e * DM + n0 + lrow) * KP + lch * 8;
    const __nv_bfloat16* bLoSrc =
        g_Wlo + ((size_t)e * DM + n0 + lrow) * KP + lch * 8;
    uint32_t smoff = lrow * 48 + lch * 16;

    // prologue: stages 0..NSTG-2
#pragma unroll
    for (int s = 0; s < NSTG - 1; s++) {
        uint32_t sb = dynb + s * STAGE;
        cp16(sb + AHI + smoff, aHiSrc + s * 16);
        cp16(sb + ALO + smoff, aLoSrc + s * 16);
        cp16(sb + BHI + smoff, bHiSrc + s * 16);
        cp16(sb + BLO + smoff, bLoSrc + s * 16);
        cp_commit();
    }

    float acc[4][4][4];
#pragma unroll
    for (int i = 0; i < 4; i++)
#pragma unroll
        for (int j = 0; j < 4; j++)
#pragma unroll
            for (int q = 0; q < 4; q++) acc[i][j][q] = 0.f;

    // fragment address offsets
    int l7 = lane & 7;
    uint32_t aRowOff = (uint32_t)((wm * 64 + l7 + ((lane >> 3) & 1) * 8) * 48
                                  + ((lane >> 4) & 1) * 16);
    int bl = lane & 15;
    uint32_t bRowOff = (uint32_t)((wn * 32 + (bl & 7)) * 48 + ((bl >> 3) & 1) * 16);

    for (int ks = 0; ks < NK16; ks++) {
        cp_wait<NSTG - 2>();
        __syncthreads();   // single barrier per k-step

        // issue next stage immediately (overwrites stage read 2 iters ago:
        // all its readers are program-order-before this barrier)
        int ns = ks + NSTG - 1;
        if (ns < NK16) {
            uint32_t nb = dynb + (ns % NSTG) * STAGE;
            cp16(nb + AHI + smoff, aHiSrc + ns * 16);
            cp16(nb + ALO + smoff, aLoSrc + ns * 16);
            cp16(nb + BHI + smoff, bHiSrc + ns * 16);
            cp16(nb + BLO + smoff, bLoSrc + ns * 16);
        }
        cp_commit();

        uint32_t sb = dynb + (ks % NSTG) * STAGE;

        uint32_t bh[4][2], blo[4][2];
#pragma unroll
        for (int tn = 0; tn < 4; tn++) {
            uint32_t ba = sb + BHI + bRowOff + tn * 8 * 48;
            ldm_x2(bh[tn], ba);
            ldm_x2(blo[tn], ba + (BLO - BHI));
        }
#pragma unroll
        for (int tm = 0; tm < 4; tm++) {
            uint32_t aa = sb + AHI + aRowOff + tm * 16 * 48;
            uint32_t ah[4], al[4];
            ldm_x4(ah, aa);
            ldm_x4(al, aa + (ALO - AHI));
#pragma unroll
            for (int tn = 0; tn < 4; tn++) {
                MMA_BF16(acc[tm][tn], ah, bh[tn]);
                MMA_BF16(acc[tm][tn], ah, blo[tn]);
                MMA_BF16(acc[tm][tn], al, bh[tn]);
            }
        }
    }

    // epilogue: bias + gate, write to scratch
    int rq = lane >> 2, cq = (lane & 3) * 2;
#pragma unroll
    for (int tm = 0; tm < 4; tm++) {
        int r0 = wm * 64 + tm * 16 + rq;
        int r1 = r0 + 8;
#pragma unroll
        for (int tn = 0; tn < 4; tn++) {
            int cl = wn * 32 + tn * 8 + cq;
            float b0 = sBias[cl], b1 = sBias[cl + 1];
            if (r0 < rows) {
                float g = sGate[r0];
                float2 o = make_float2(g * (acc[tm][tn][0] + b0),
                                       g * (acc[tm][tn][1] + b1));
                *(float2*)(g_scratch + (size_t)sEntry[r0] * DM + n0 + cl) = o;
            }
            if (r1 < rows) {
                float g = sGate[r1];
                float2 o = make_float2(g * (acc[tm][tn][2] + b0),
                                       g * (acc[tm][tn][3] + b1));
                *(float2*)(g_scratch + (size_t)sEntry[r1] * DM + n0 + cl) = o;
            }
        }
    }
}

// ---------------------------------------------------------------------------
__global__ void combine_kernel(float* __restrict__ out) {
    int idx = blockIdx.x * blockDim.x + threadIdx.x;
    int b   = idx >> 7;
    int m4  = (idx & 127) << 2;
    float g1 = g_gate[2 * b], g2 = g_gate[2 * b + 1];
    float4 v = make_float4(0.f, 0.f, 0.f, 0.f);
    if (g1 > 0.f) {
        float4 s = *(const float4*)(g_scratch + (size_t)(2 * b) * DM + m4);
        v.x += s.x; v.y += s.y; v.z += s.z; v.w += s.w;
    }
    if (g2 > 0.f) {
        float4 s = *(const float4*)(g_scratch + (size_t)(2 * b + 1) * DM + m4);
        v.x += s.x; v.y += s.y; v.z += s.z; v.w += s.w;
    }
    float4 o;
    o.x = __bfloat162float(__float2bfloat16(v.x));
    o.y = __bfloat162float(__float2bfloat16(v.y));
    o.z = __bfloat162float(__float2bfloat16(v.z));
    o.w = __bfloat162float(__float2bfloat16(v.w));
    ((float4*)out)[idx] = o;
}

// ---------------------------------------------------------------------------
extern "C" void kernel_launch(void* const* d_in, const int* in_sizes, int n_in,
                              void* d_out, int out_size)
{
    const float* X      = (const float*)d_in[0];
    const float* logits = (const float*)d_in[1];
    const int*   masks  = (const int*)  d_in[2];
    const float* selemb = (const float*)d_in[3];
    const float* W      = (const float*)d_in[4];
    const float* bias   = (const float*)d_in[5];
    float* out = (float*)d_out;

    cudaFuncSetAttribute(gemm_kernel,
                         cudaFuncAttributeMaxDynamicSharedMemorySize, DYNSM);

    init_kernel<<<1, 32>>>();
    split_x_kernel<<<(int)(((size_t)NB * KP + 255) / 256), 256>>>(X);
    dim3 wg((KP + 31) / 32, DM / 32, NE);
    split_w_kernel<<<wg, dim3(32, 8)>>>(W);
    phaseA_kernel<<<NB / 32, 1024>>>(logits, masks, selemb, out);
    guide_kernel<<<1, 512>>>(out);
    dim3 g(NB / 128, DM / 128, NE);
    gemm_kernel<<<g, 256, DYNSM>>>(bias);
    combine_kernel<<<(NB * DM / 4) / 256, 256>>>(out);
}

// round 6
// speedup vs baseline: 2.1984x; 1.0266x over previous
#include <cuda_runtime.h>
#include <cuda_bf16.h>
#include <cstdint>

#define NB   16384
#define NE   8
#define DIN  900
#define DM   512
#define DSEL 128
#define EPSF 1e-9f

#define KP     912            // 57 * 16, zero-padded K
#define NK16   57
#define NSTG   3              // cp.async pipeline depth
#define STAGE  24576          // bytes per stage: 4 arrays * 128 rows * 48B
#define AHI    0
#define ALO    6144
#define BHI    12288
#define BLO    18432
#define DYNSM  (NSTG * STAGE) // 73728

#define OUT_GUIDE (NB * DM)
#define OUT_SEL   (NB * DM + 1)

__device__ float g_scratch[(size_t)2 * NB * DM];     // gated per-(token,slot) outputs
__device__ int   g_bucket[NE * NB];
__device__ int   g_count[NE];
__device__ float g_gate[2 * NB];
__device__ float g_partial[512];
__device__ __nv_bfloat16 g_Xhi[(size_t)NB * KP];
__device__ __nv_bfloat16 g_Xlo[(size_t)NB * KP];
__device__ __nv_bfloat16 g_Whi[(size_t)NE * DM * KP];   // W transposed [e][n][k]
__device__ __nv_bfloat16 g_Wlo[(size_t)NE * DM * KP];

// ---------------------------------------------------------------------------
__device__ __forceinline__ uint32_t smem_u32(const void* p) {
    return (uint32_t)__cvta_generic_to_shared(p);
}
__device__ __forceinline__ void cp16(uint32_t s, const void* g) {
    asm volatile("cp.async.cg.shared.global [%0], [%1], 16;" :: "r"(s), "l"(g));
}
__device__ __forceinline__ void cp_commit() {
    asm volatile("cp.async.commit_group;" ::: "memory");
}
template <int N>
__device__ __forceinline__ void cp_wait() {
    asm volatile("cp.async.wait_group %0;" :: "n"(N) : "memory");
}
__device__ __forceinline__ void ldm_x4(uint32_t* r, uint32_t a) {
    asm volatile("ldmatrix.sync.aligned.m8n8.x4.shared.b16 {%0,%1,%2,%3}, [%4];"
                 : "=r"(r[0]), "=r"(r[1]), "=r"(r[2]), "=r"(r[3]) : "r"(a));
}
#define MMA_BF16(acc, a, b) \
    asm volatile("mma.sync.aligned.m16n8k16.row.col.f32.bf16.bf16.f32 " \
        "{%0,%1,%2,%3}, {%4,%5,%6,%7}, {%8,%9}, {%0,%1,%2,%3};" \
        : "+f"((acc)[0]), "+f"((acc)[1]), "+f"((acc)[2]), "+f"((acc)[3]) \
        : "r"((a)[0]), "r"((a)[1]), "r"((a)[2]), "r"((a)[3]), \
          "r"((b)[0]), "r"((b)[1]))

// ---------------------------------------------------------------------------
__global__ void init_kernel() {
    int t = threadIdx.x;
    if (t < NE) g_count[t] = 0;
}

// ---------------------------------------------------------------------------
// Split X into bf16 hi/lo, pad K to 912 with zeros.
__global__ void split_x_kernel(const float* __restrict__ X) {
    size_t i = (size_t)blockIdx.x * blockDim.x + threadIdx.x;
    if (i >= (size_t)NB * KP) return;
    int b = (int)(i / KP), k = (int)(i % KP);
    float v = (k < DIN) ? X[(size_t)b * DIN + k] : 0.f;
    __nv_bfloat16 h = __float2bfloat16(v);
    g_Xhi[i] = h;
    g_Xlo[i] = __float2bfloat16(v - __bfloat162float(h));
}

// ---------------------------------------------------------------------------
// Transpose + split W[e][k][n] -> [e][n][kpad] bf16 hi/lo.
__global__ void split_w_kernel(const float* __restrict__ W) {
    __shared__ float tile[32][33];
    int e = blockIdx.z;
    int k0 = blockIdx.x * 32;
    int n0 = blockIdx.y * 32;
    int tx = threadIdx.x, ty = threadIdx.y;
#pragma unroll
    for (int i = 0; i < 4; i++) {
        int k = k0 + ty + i * 8;
        tile[ty + i * 8][tx] = (k < DIN) ? W[((size_t)e * DIN + k) * DM + n0 + tx] : 0.f;
    }
    __syncthreads();
#pragma unroll
    for (int i = 0; i < 4; i++) {
        int n = n0 + ty + i * 8;
        int kk = k0 + tx;
        if (kk < KP) {
            float v = tile[tx][ty + i * 8];
            __nv_bfloat16 h = __float2bfloat16(v);
            size_t idx = ((size_t)e * DM + n) * KP + kk;
            g_Whi[idx] = h;
            g_Wlo[idx] = __float2bfloat16(v - __bfloat162float(h));
        }
    }
}

// ---------------------------------------------------------------------------
// Phase A (unchanged, proven): softmax, inactive mixture, top-2, bucketing.
__global__ void __launch_bounds__(1024) phaseA_kernel(
    const float* __restrict__ logits,
    const int*   __restrict__ masks,
    const float* __restrict__ selemb,
    float*       __restrict__ out)
{
    __shared__ int   lcount[NE];
    __shared__ int   lbase[NE];
    __shared__ int   staging[NE][32];
    __shared__ float warpS[32];

    int tid  = threadIdx.x;
    int warp = tid >> 5;
    int lane = tid & 31;
    if (tid < NE) lcount[tid] = 0;
    __syncthreads();

    int b = blockIdx.x * 32 + warp;

    float raw[NE];
    float mx = -1e30f;
#pragma unroll
    for (int e = 0; e < NE; e++) { raw[e] = logits[b * NE + e]; mx = fmaxf(mx, raw[e]); }
    float sum = 0.f;
#pragma unroll
    for (int e = 0; e < NE; e++) { raw[e] = expf(raw[e] - mx); sum += raw[e]; }
    float inv = 1.f / sum;
    int m[NE];
#pragma unroll
    for (int e = 0; e < NE; e++) { raw[e] *= inv; m[e] = masks[b * NE + e]; }

    float w[NE]; float isum = 0.f;
#pragma unroll
    for (int e = 0; e < NE; e++) { w[e] = (m[e] == 1) ? 0.f : raw[e]; isum += w[e]; }
    float winv = 1.f / (isum + EPSF);

    float a[NE]; float srow = 0.f;
#pragma unroll
    for (int e = 0; e < NE; e++) {
        w[e] *= winv;
        a[e] = (m[e] == 1) ? raw[e] : 0.f;
        srow += a[e];
    }

    float v1 = -1.f, v2 = -1.f; int e1 = 0, e2 = 0;
#pragma unroll
    for (int e = 0; e < NE; e++) {
        if (a[e] > v1) { v2 = v1; e2 = e1; v1 = a[e]; e1 = e; }
        else if (a[e] > v2) { v2 = a[e]; e2 = e; }
    }
    float gs = 1.f / (v1 + v2 + EPSF);
    float g1 = v1 * gs, g2 = v2 * gs;

    const float4* base = (const float4*)(selemb + (size_t)b * NE * DSEL);
    float4 acc = make_float4(0.f, 0.f, 0.f, 0.f);
#pragma unroll
    for (int e = 0; e < NE; e++) {
        float4 v = base[e * (DSEL / 4) + lane];
        acc.x += w[e] * v.x; acc.y += w[e] * v.y;
        acc.z += w[e] * v.z; acc.w += w[e] * v.w;
    }
    float* dst = out + OUT_SEL + (size_t)b * DSEL + lane * 4;
    dst[0] = acc.x; dst[1] = acc.y; dst[2] = acc.z; dst[3] = acc.w;

    if (lane == 0) {
        g_gate[2 * b]     = g1;
        g_gate[2 * b + 1] = g2;
        if (g1 > 0.f) { int p = atomicAdd(&lcount[e1], 1); staging[e1][p] = 2 * b; }
        if (g2 > 0.f) { int p = atomicAdd(&lcount[e2], 1); staging[e2][p] = 2 * b + 1; }
        warpS[warp] = srow;
    }
    __syncthreads();
    if (tid < NE) lbase[tid] = atomicAdd(&g_count[tid], lcount[tid]);
    if (tid == 0) {
        float s = 0.f;
        for (int i = 0; i < 32; i++) s += warpS[i];
        g_partial[blockIdx.x] = s;
    }
    __syncthreads();
#pragma unroll
    for (int e = 0; e < NE; e++) {
        for (int i = tid; i < lcount[e]; i += blockDim.x)
            g_bucket[e * NB + lbase[e] + i] = staging[e][i];
    }
}

// ---------------------------------------------------------------------------
__global__ void guide_kernel(float* __restrict__ out) {
    __shared__ float sm[512];
    int t = threadIdx.x;
    sm[t] = g_partial[t];
    __syncthreads();
    for (int s = 256; s > 0; s >>= 1) {
        if (t < s) sm[t] += sm[t + s];
        __syncthreads();
    }
    if (t == 0) {
        float sv = sm[0] / (float)NB;
        float d = 1.f - sv;
        out[OUT_GUIDE] = d * d;
    }
}

// ---------------------------------------------------------------------------
// Tensor-core grouped GEMM: mma.sync bf16, 3-pass hi/lo split.
// CTA tile 128x128, BK=16, 3-stage cp.async pipeline, 8 warps (2m x 4n),
// 2 CTAs/SM, one barrier per k-step, B via ldm_x4, A-frag double buffering.
extern __shared__ char sm_dyn[];

__global__ void __launch_bounds__(256, 2) gemm_kernel(
    const float* __restrict__ bias)
{
    int e   = blockIdx.z;
    int cnt = g_count[e];
    int rt0 = blockIdx.x * 128;
    if (rt0 >= cnt) return;
    int rows = cnt - rt0; if (rows > 128) rows = 128;
    int n0 = blockIdx.y * 128;

    __shared__ int   sEntry[128];
    __shared__ float sGate[128];
    __shared__ float sBias[128];

    int t = threadIdx.x;
    int wid = t >> 5, lane = t & 31;
    int wm = wid & 1, wn = wid >> 1;       // 2 x 4 warp grid

    if (t < 128) {
        int entry = 0; float g = 0.f;
        if (t < rows) { entry = g_bucket[e * NB + rt0 + t]; g = g_gate[entry]; }
        sEntry[t] = entry; sGate[t] = g;
        sBias[t]  = bias[e * DM + n0 + t];
    }
    __syncthreads();

    uint32_t dynb = smem_u32(sm_dyn);

    // per-thread cp.async sources: row = t>>1, chunk = t&1 (16B each)
    int lrow = t >> 1, lch = t & 1;
    const __nv_bfloat16* aHiSrc =
        g_Xhi + (size_t)(sEntry[lrow] >> 1) * KP + lch * 8;
    const __nv_bfloat16* aLoSrc =
        g_Xlo + (size_t)(sEntry[lrow] >> 1) * KP + lch * 8;
    const __nv_bfloat16* bHiSrc =
        g_Whi + ((size_t)e * DM + n0 + lrow) * KP + lch * 8;
    const __nv_bfloat16* bLoSrc =
        g_Wlo + ((size_t)e * DM + n0 + lrow) * KP + lch * 8;
    uint32_t smoff = lrow * 48 + lch * 16;

    // prologue: stages 0..NSTG-2
#pragma unroll
    for (int s = 0; s < NSTG - 1; s++) {
        uint32_t sb = dynb + s * STAGE;
        cp16(sb + AHI + smoff, aHiSrc + s * 16);
        cp16(sb + ALO + smoff, aLoSrc + s * 16);
        cp16(sb + BHI + smoff, bHiSrc + s * 16);
        cp16(sb + BLO + smoff, bLoSrc + s * 16);
        cp_commit();
    }

    float acc[4][4][4];
#pragma unroll
    for (int i = 0; i < 4; i++)
#pragma unroll
        for (int j = 0; j < 4; j++)
#pragma unroll
            for (int q = 0; q < 4; q++) acc[i][j][q] = 0.f;

    // fragment address offsets
    int l7 = lane & 7;
    uint32_t aRowOff = (uint32_t)((wm * 64 + l7 + ((lane >> 3) & 1) * 8) * 48
                                  + ((lane >> 4) & 1) * 16);
    // B via ldm_x4: one x4 gives two adjacent tn fragments (8+8 cols)
    uint32_t bRow4Off = (uint32_t)((wn * 32 + ((lane >> 4) & 1) * 8 + l7) * 48
                                   + ((lane >> 3) & 1) * 16);

    for (int ks = 0; ks < NK16; ks++) {
        cp_wait<NSTG - 2>();
        __syncthreads();   // single barrier per k-step

        // issue next stage immediately (overwrites stage read 2 iters ago:
        // all its readers are program-order-before this barrier)
        int ns = ks + NSTG - 1;
        if (ns < NK16) {
            uint32_t nb = dynb + (ns % NSTG) * STAGE;
            cp16(nb + AHI + smoff, aHiSrc + ns * 16);
            cp16(nb + ALO + smoff, aLoSrc + ns * 16);
            cp16(nb + BHI + smoff, bHiSrc + ns * 16);
            cp16(nb + BLO + smoff, bLoSrc + ns * 16);
        }
        cp_commit();

        uint32_t sb = dynb + (ks % NSTG) * STAGE;

        // B fragments: 4 ldm_x4 (hi/lo x two tn-pairs)
        uint32_t bh[4][2], blo[4][2];
#pragma unroll
        for (int p = 0; p < 2; p++) {
            uint32_t r4[4];
            uint32_t ba = sb + BHI + bRow4Off + p * 16 * 48;
            ldm_x4(r4, ba);
            bh[2 * p][0] = r4[0]; bh[2 * p][1] = r4[1];
            bh[2 * p + 1][0] = r4[2]; bh[2 * p + 1][1] = r4[3];
            ldm_x4(r4, ba + (BLO - BHI));
            blo[2 * p][0] = r4[0]; blo[2 * p][1] = r4[1];
            blo[2 * p + 1][0] = r4[2]; blo[2 * p + 1][1] = r4[3];
        }

        // A fragments: double-buffered across tm
        uint32_t ah[2][4], al[2][4];
        {
            uint32_t aa = sb + AHI + aRowOff;
            ldm_x4(ah[0], aa);
            ldm_x4(al[0], aa + (ALO - AHI));
        }
#pragma unroll
        for (int tm = 0; tm < 4; tm++) {
            int cur = tm & 1;
            if (tm < 3) {
                uint32_t aa = sb + AHI + aRowOff + (tm + 1) * 16 * 48;
                ldm_x4(ah[cur ^ 1], aa);
                ldm_x4(al[cur ^ 1], aa + (ALO - AHI));
            }
#pragma unroll
            for (int tn = 0; tn < 4; tn++) {
                MMA_BF16(acc[tm][tn], ah[cur], bh[tn]);
                MMA_BF16(acc[tm][tn], ah[cur], blo[tn]);
                MMA_BF16(acc[tm][tn], al[cur], bh[tn]);
            }
        }
    }

    // epilogue: bias + gate, write to scratch
    int rq = lane >> 2, cq = (lane & 3) * 2;
#pragma unroll
    for (int tm = 0; tm < 4; tm++) {
        int r0 = wm * 64 + tm * 16 + rq;
        int r1 = r0 + 8;
#pragma unroll
        for (int tn = 0; tn < 4; tn++) {
            int cl = wn * 32 + tn * 8 + cq;
            float b0 = sBias[cl], b1 = sBias[cl + 1];
            if (r0 < rows) {
                float g = sGate[r0];
                float2 o = make_float2(g * (acc[tm][tn][0] + b0),
                                       g * (acc[tm][tn][1] + b1));
                *(float2*)(g_scratch + (size_t)sEntry[r0] * DM + n0 + cl) = o;
            }
            if (r1 < rows) {
                float g = sGate[r1];
                float2 o = make_float2(g * (acc[tm][tn][2] + b0),
                                       g * (acc[tm][tn][3] + b1));
                *(float2*)(g_scratch + (size_t)sEntry[r1] * DM + n0 + cl) = o;
            }
        }
    }
}

// ---------------------------------------------------------------------------
__global__ void combine_kernel(float* __restrict__ out) {
    int idx = blockIdx.x * blockDim.x + threadIdx.x;
    int b   = idx >> 7;
    int m4  = (idx & 127) << 2;
    float g1 = g_gate[2 * b], g2 = g_gate[2 * b + 1];
    float4 v = make_float4(0.f, 0.f, 0.f, 0.f);
    if (g1 > 0.f) {
        float4 s = *(const float4*)(g_scratch + (size_t)(2 * b) * DM + m4);
        v.x += s.x; v.y += s.y; v.z += s.z; v.w += s.w;
    }
    if (g2 > 0.f) {
        float4 s = *(const float4*)(g_scratch + (size_t)(2 * b + 1) * DM + m4);
        v.x += s.x; v.y += s.y; v.z += s.z; v.w += s.w;
    }
    float4 o;
    o.x = __bfloat162float(__float2bfloat16(v.x));
    o.y = __bfloat162float(__float2bfloat16(v.y));
    o.z = __bfloat162float(__float2bfloat16(v.z));
    o.w = __bfloat162float(__float2bfloat16(v.w));
    ((float4*)out)[idx] = o;
}

// ---------------------------------------------------------------------------
extern "C" void kernel_launch(void* const* d_in, const int* in_sizes, int n_in,
                              void* d_out, int out_size)
{
    const float* X      = (const float*)d_in[0];
    const float* logits = (const float*)d_in[1];
    const int*   masks  = (const int*)  d_in[2];
    const float* selemb = (const float*)d_in[3];
    const float* W      = (const float*)d_in[4];
    const float* bias   = (const float*)d_in[5];
    float* out = (float*)d_out;

    cudaFuncSetAttribute(gemm_kernel,
                         cudaFuncAttributeMaxDynamicSharedMemorySize, DYNSM);

    init_kernel<<<1, 32>>>();
    split_x_kernel<<<(int)(((size_t)NB * KP + 255) / 256), 256>>>(X);
    dim3 wg((KP + 31) / 32, DM / 32, NE);
    split_w_kernel<<<wg, dim3(32, 8)>>>(W);
    phaseA_kernel<<<NB / 32, 1024>>>(logits, masks, selemb, out);
    guide_kernel<<<1, 512>>>(out);
    dim3 g(NB / 128, DM / 128, NE);
    gemm_kernel<<<g, 256, DYNSM>>>(bias);
    combine_kernel<<<(NB * DM / 4) / 256, 256>>>(out);
}

// round 7
// speedup vs baseline: 2.2088x; 1.0047x over previous
#include <cuda_runtime.h>
#include <cuda_bf16.h>
#include <cstdint>

#define NB   16384
#define NE   8
#define DIN  900
#define DM   512
#define DSEL 128
#define EPSF 1e-9f

#define KP     912            // 57 * 16, zero-padded K
#define NK16   57
#define NSTG   3              // cp.async pipeline depth
#define STAGE  24576          // bytes per stage: 4 arrays * 128 rows * 48B
#define AHI    0
#define ALO    6144
#define BHI    12288
#define BLO    18432
#define DYNSM  (NSTG * STAGE) // 73728

#define OUT_GUIDE (NB * DM)
#define OUT_SEL   (NB * DM + 1)

__device__ float g_scratch[(size_t)2 * NB * DM];     // gated per-(token,slot) outputs
__device__ int   g_bucket[NE * NB];
__device__ int   g_count[NE];
__device__ float g_gate[2 * NB];
__device__ float g_partial[512];
__device__ __nv_bfloat16 g_Xhi[(size_t)NB * KP];
__device__ __nv_bfloat16 g_Xlo[(size_t)NB * KP];
__device__ __nv_bfloat16 g_Whi[(size_t)NE * DM * KP];   // W transposed [e][n][k]
__device__ __nv_bfloat16 g_Wlo[(size_t)NE * DM * KP];

// ---------------------------------------------------------------------------
__device__ __forceinline__ uint32_t smem_u32(const void* p) {
    return (uint32_t)__cvta_generic_to_shared(p);
}
__device__ __forceinline__ void cp16(uint32_t s, const void* g) {
    asm volatile("cp.async.cg.shared.global [%0], [%1], 16;" :: "r"(s), "l"(g));
}
__device__ __forceinline__ void cp_commit() {
    asm volatile("cp.async.commit_group;" ::: "memory");
}
template <int N>
__device__ __forceinline__ void cp_wait() {
    asm volatile("cp.async.wait_group %0;" :: "n"(N) : "memory");
}
__device__ __forceinline__ void ldm_x4(uint32_t* r, uint32_t a) {
    asm volatile("ldmatrix.sync.aligned.m8n8.x4.shared.b16 {%0,%1,%2,%3}, [%4];"
                 : "=r"(r[0]), "=r"(r[1]), "=r"(r[2]), "=r"(r[3]) : "r"(a));
}
#define MMA_BF16(acc, a, b) \
    asm volatile("mma.sync.aligned.m16n8k16.row.col.f32.bf16.bf16.f32 " \
        "{%0,%1,%2,%3}, {%4,%5,%6,%7}, {%8,%9}, {%0,%1,%2,%3};" \
        : "+f"((acc)[0]), "+f"((acc)[1]), "+f"((acc)[2]), "+f"((acc)[3]) \
        : "r"((a)[0]), "r"((a)[1]), "r"((a)[2]), "r"((a)[3]), \
          "r"((b)[0]), "r"((b)[1]))

// ---------------------------------------------------------------------------
__global__ void init_kernel() {
    int t = threadIdx.x;
    if (t < NE) g_count[t] = 0;
}

// ---------------------------------------------------------------------------
// Split X into bf16 hi/lo, pad K to 912 with zeros.
__global__ void split_x_kernel(const float* __restrict__ X) {
    size_t i = (size_t)blockIdx.x * blockDim.x + threadIdx.x;
    if (i >= (size_t)NB * KP) return;
    int b = (int)(i / KP), k = (int)(i % KP);
    float v = (k < DIN) ? X[(size_t)b * DIN + k] : 0.f;
    __nv_bfloat16 h = __float2bfloat16(v);
    g_Xhi[i] = h;
    g_Xlo[i] = __float2bfloat16(v - __bfloat162float(h));
}

// ---------------------------------------------------------------------------
// Transpose + split W[e][k][n] -> [e][n][kpad] bf16 hi/lo.
__global__ void split_w_kernel(const float* __restrict__ W) {
    __shared__ float tile[32][33];
    int e = blockIdx.z;
    int k0 = blockIdx.x * 32;
    int n0 = blockIdx.y * 32;
    int tx = threadIdx.x, ty = threadIdx.y;
#pragma unroll
    for (int i = 0; i < 4; i++) {
        int k = k0 + ty + i * 8;
        tile[ty + i * 8][tx] = (k < DIN) ? W[((size_t)e * DIN + k) * DM + n0 + tx] : 0.f;
    }
    __syncthreads();
#pragma unroll
    for (int i = 0; i < 4; i++) {
        int n = n0 + ty + i * 8;
        int kk = k0 + tx;
        if (kk < KP) {
            float v = tile[tx][ty + i * 8];
            __nv_bfloat16 h = __float2bfloat16(v);
            size_t idx = ((size_t)e * DM + n) * KP + kk;
            g_Whi[idx] = h;
            g_Wlo[idx] = __float2bfloat16(v - __bfloat162float(h));
        }
    }
}

// ---------------------------------------------------------------------------
// Phase A (unchanged, proven): softmax, inactive mixture, top-2, bucketing.
__global__ void __launch_bounds__(1024) phaseA_kernel(
    const float* __restrict__ logits,
    const int*   __restrict__ masks,
    const float* __restrict__ selemb,
    float*       __restrict__ out)
{
    __shared__ int   lcount[NE];
    __shared__ int   lbase[NE];
    __shared__ int   staging[NE][32];
    __shared__ float warpS[32];

    int tid  = threadIdx.x;
    int warp = tid >> 5;
    int lane = tid & 31;
    if (tid < NE) lcount[tid] = 0;
    __syncthreads();

    int b = blockIdx.x * 32 + warp;

    float raw[NE];
    float mx = -1e30f;
#pragma unroll
    for (int e = 0; e < NE; e++) { raw[e] = logits[b * NE + e]; mx = fmaxf(mx, raw[e]); }
    float sum = 0.f;
#pragma unroll
    for (int e = 0; e < NE; e++) { raw[e] = expf(raw[e] - mx); sum += raw[e]; }
    float inv = 1.f / sum;
    int m[NE];
#pragma unroll
    for (int e = 0; e < NE; e++) { raw[e] *= inv; m[e] = masks[b * NE + e]; }

    float w[NE]; float isum = 0.f;
#pragma unroll
    for (int e = 0; e < NE; e++) { w[e] = (m[e] == 1) ? 0.f : raw[e]; isum += w[e]; }
    float winv = 1.f / (isum + EPSF);

    float a[NE]; float srow = 0.f;
#pragma unroll
    for (int e = 0; e < NE; e++) {
        w[e] *= winv;
        a[e] = (m[e] == 1) ? raw[e] : 0.f;
        srow += a[e];
    }

    float v1 = -1.f, v2 = -1.f; int e1 = 0, e2 = 0;
#pragma unroll
    for (int e = 0; e < NE; e++) {
        if (a[e] > v1) { v2 = v1; e2 = e1; v1 = a[e]; e1 = e; }
        else if (a[e] > v2) { v2 = a[e]; e2 = e; }
    }
    float gs = 1.f / (v1 + v2 + EPSF);
    float g1 = v1 * gs, g2 = v2 * gs;

    const float4* base = (const float4*)(selemb + (size_t)b * NE * DSEL);
    float4 acc = make_float4(0.f, 0.f, 0.f, 0.f);
#pragma unroll
    for (int e = 0; e < NE; e++) {
        float4 v = base[e * (DSEL / 4) + lane];
        acc.x += w[e] * v.x; acc.y += w[e] * v.y;
        acc.z += w[e] * v.z; acc.w += w[e] * v.w;
    }
    float* dst = out + OUT_SEL + (size_t)b * DSEL + lane * 4;
    dst[0] = acc.x; dst[1] = acc.y; dst[2] = acc.z; dst[3] = acc.w;

    if (lane == 0) {
        g_gate[2 * b]     = g1;
        g_gate[2 * b + 1] = g2;
        if (g1 > 0.f) { int p = atomicAdd(&lcount[e1], 1); staging[e1][p] = 2 * b; }
        if (g2 > 0.f) { int p = atomicAdd(&lcount[e2], 1); staging[e2][p] = 2 * b + 1; }
        warpS[warp] = srow;
    }
    __syncthreads();
    if (tid < NE) lbase[tid] = atomicAdd(&g_count[tid], lcount[tid]);
    if (tid == 0) {
        float s = 0.f;
        for (int i = 0; i < 32; i++) s += warpS[i];
        g_partial[blockIdx.x] = s;
    }
    __syncthreads();
#pragma unroll
    for (int e = 0; e < NE; e++) {
        for (int i = tid; i < lcount[e]; i += blockDim.x)
            g_bucket[e * NB + lbase[e] + i] = staging[e][i];
    }
}

// ---------------------------------------------------------------------------
__global__ void guide_kernel(float* __restrict__ out) {
    __shared__ float sm[512];
    int t = threadIdx.x;
    sm[t] = g_partial[t];
    __syncthreads();
    for (int s = 256; s > 0; s >>= 1) {
        if (t < s) sm[t] += sm[t + s];
        __syncthreads();
    }
    if (t == 0) {
        float sv = sm[0] / (float)NB;
        float d = 1.f - sv;
        out[OUT_GUIDE] = d * d;
    }
}

// ---------------------------------------------------------------------------
// Tensor-core grouped GEMM: mma.sync bf16, 3-pass hi/lo split.
// CTA tile 128x128, BK=16, 3-stage cp.async pipeline, 8 warps (2m x 4n),
// 2 CTAs/SM, one barrier per k-step. MMAs issued PASS-MAJOR so consecutive
// instructions hit independent accumulators (no RAW chains on acc).
extern __shared__ char sm_dyn[];

__global__ void __launch_bounds__(256, 2) gemm_kernel(
    const float* __restrict__ bias)
{
    int e   = blockIdx.z;
    int cnt = g_count[e];
    int rt0 = blockIdx.x * 128;
    if (rt0 >= cnt) return;
    int rows = cnt - rt0; if (rows > 128) rows = 128;
    int n0 = blockIdx.y * 128;

    __shared__ int   sEntry[128];
    __shared__ float sGate[128];
    __shared__ float sBias[128];

    int t = threadIdx.x;
    int wid = t >> 5, lane = t & 31;
    int wm = wid & 1, wn = wid >> 1;       // 2 x 4 warp grid

    if (t < 128) {
        int entry = 0; float g = 0.f;
        if (t < rows) { entry = g_bucket[e * NB + rt0 + t]; g = g_gate[entry]; }
        sEntry[t] = entry; sGate[t] = g;
        sBias[t]  = bias[e * DM + n0 + t];
    }
    __syncthreads();

    uint32_t dynb = smem_u32(sm_dyn);

    // per-thread cp.async sources: row = t>>1, chunk = t&1 (16B each)
    int lrow = t >> 1, lch = t & 1;
    const __nv_bfloat16* aHiSrc =
        g_Xhi + (size_t)(sEntry[lrow] >> 1) * KP + lch * 8;
    const __nv_bfloat16* aLoSrc =
        g_Xlo + (size_t)(sEntry[lrow] >> 1) * KP + lch * 8;
    const __nv_bfloat16* bHiSrc =
        g_Whi + ((size_t)e * DM + n0 + lrow) * KP + lch * 8;
    const __nv_bfloat16* bLoSrc =
        g_Wlo + ((size_t)e * DM + n0 + lrow) * KP + lch * 8;
    uint32_t smoff = lrow * 48 + lch * 16;

    // prologue: stages 0..NSTG-2
#pragma unroll
    for (int s = 0; s < NSTG - 1; s++) {
        uint32_t sb = dynb + s * STAGE;
        cp16(sb + AHI + smoff, aHiSrc + s * 16);
        cp16(sb + ALO + smoff, aLoSrc + s * 16);
        cp16(sb + BHI + smoff, bHiSrc + s * 16);
        cp16(sb + BLO + smoff, bLoSrc + s * 16);
        cp_commit();
    }

    float acc[4][4][4];
#pragma unroll
    for (int i = 0; i < 4; i++)
#pragma unroll
        for (int j = 0; j < 4; j++)
#pragma unroll
            for (int q = 0; q < 4; q++) acc[i][j][q] = 0.f;

    // fragment address offsets
    int l7 = lane & 7;
    uint32_t aRowOff = (uint32_t)((wm * 64 + l7 + ((lane >> 3) & 1) * 8) * 48
                                  + ((lane >> 4) & 1) * 16);
    // B via ldm_x4: one x4 gives two adjacent tn fragments (8+8 cols)
    uint32_t bRow4Off = (uint32_t)((wn * 32 + ((lane >> 4) & 1) * 8 + l7) * 48
                                   + ((lane >> 3) & 1) * 16);

    for (int ks = 0; ks < NK16; ks++) {
        cp_wait<NSTG - 2>();
        __syncthreads();   // single barrier per k-step

        // issue next stage immediately (overwrites stage read 2 iters ago:
        // all its readers are program-order-before this barrier)
        int ns = ks + NSTG - 1;
        if (ns < NK16) {
            uint32_t nb = dynb + (ns % NSTG) * STAGE;
            cp16(nb + AHI + smoff, aHiSrc + ns * 16);
            cp16(nb + ALO + smoff, aLoSrc + ns * 16);
            cp16(nb + BHI + smoff, bHiSrc + ns * 16);
            cp16(nb + BLO + smoff, bLoSrc + ns * 16);
        }
        cp_commit();

        uint32_t sb = dynb + (ks % NSTG) * STAGE;

        // B fragments: 4 ldm_x4 (hi/lo x two tn-pairs)
        uint32_t bh[4][2], blo[4][2];
#pragma unroll
        for (int p = 0; p < 2; p++) {
            uint32_t r4[4];
            uint32_t ba = sb + BHI + bRow4Off + p * 16 * 48;
            ldm_x4(r4, ba);
            bh[2 * p][0] = r4[0]; bh[2 * p][1] = r4[1];
            bh[2 * p + 1][0] = r4[2]; bh[2 * p + 1][1] = r4[3];
            ldm_x4(r4, ba + (BLO - BHI));
            blo[2 * p][0] = r4[0]; blo[2 * p][1] = r4[1];
            blo[2 * p + 1][0] = r4[2]; blo[2 * p + 1][1] = r4[3];
        }

        // A fragments: double-buffered across tm
        uint32_t ah[2][4], al[2][4];
        {
            uint32_t aa = sb + AHI + aRowOff;
            ldm_x4(ah[0], aa);
            ldm_x4(al[0], aa + (ALO - AHI));
        }
#pragma unroll
        for (int tm = 0; tm < 4; tm++) {
            int cur = tm & 1;
            if (tm < 3) {
                uint32_t aa = sb + AHI + aRowOff + (tm + 1) * 16 * 48;
                ldm_x4(ah[cur ^ 1], aa);
                ldm_x4(al[cur ^ 1], aa + (ALO - AHI));
            }
            // pass-major issue: consecutive MMAs -> independent accumulators
#pragma unroll
            for (int tn = 0; tn < 4; tn++)
                MMA_BF16(acc[tm][tn], ah[cur], bh[tn]);
#pragma unroll
            for (int tn = 0; tn < 4; tn++)
                MMA_BF16(acc[tm][tn], ah[cur], blo[tn]);
#pragma unroll
            for (int tn = 0; tn < 4; tn++)
                MMA_BF16(acc[tm][tn], al[cur], bh[tn]);
        }
    }

    // epilogue: bias + gate, write to scratch
    int rq = lane >> 2, cq = (lane & 3) * 2;
#pragma unroll
    for (int tm = 0; tm < 4; tm++) {
        int r0 = wm * 64 + tm * 16 + rq;
        int r1 = r0 + 8;
#pragma unroll
        for (int tn = 0; tn < 4; tn++) {
            int cl = wn * 32 + tn * 8 + cq;
            float b0 = sBias[cl], b1 = sBias[cl + 1];
            if (r0 < rows) {
                float g = sGate[r0];
                float2 o = make_float2(g * (acc[tm][tn][0] + b0),
                                       g * (acc[tm][tn][1] + b1));
                *(float2*)(g_scratch + (size_t)sEntry[r0] * DM + n0 + cl) = o;
            }
            if (r1 < rows) {
                float g = sGate[r1];
                float2 o = make_float2(g * (acc[tm][tn][2] + b0),
                                       g * (acc[tm][tn][3] + b1));
                *(float2*)(g_scratch + (size_t)sEntry[r1] * DM + n0 + cl) = o;
            }
        }
    }
}

// ---------------------------------------------------------------------------
__global__ void combine_kernel(float* __restrict__ out) {
    int idx = blockIdx.x * blockDim.x + threadIdx.x;
    int b   = idx >> 7;
    int m4  = (idx & 127) << 2;
    float g1 = g_gate[2 * b], g2 = g_gate[2 * b + 1];
    float4 v = make_float4(0.f, 0.f, 0.f, 0.f);
    if (g1 > 0.f) {
        float4 s = *(const float4*)(g_scratch + (size_t)(2 * b) * DM + m4);
        v.x += s.x; v.y += s.y; v.z += s.z; v.w += s.w;
    }
    if (g2 > 0.f) {
        float4 s = *(const float4*)(g_scratch + (size_t)(2 * b + 1) * DM + m4);
        v.x += s.x; v.y += s.y; v.z += s.z; v.w += s.w;
    }
    float4 o;
    o.x = __bfloat162float(__float2bfloat16(v.x));
    o.y = __bfloat162float(__float2bfloat16(v.y));
    o.z = __bfloat162float(__float2bfloat16(v.z));
    o.w = __bfloat162float(__float2bfloat16(v.w));
    ((float4*)out)[idx] = o;
}

// ---------------------------------------------------------------------------
extern "C" void kernel_launch(void* const* d_in, const int* in_sizes, int n_in,
                              void* d_out, int out_size)
{
    const float* X      = (const float*)d_in[0];
    const float* logits = (const float*)d_in[1];
    const int*   masks  = (const int*)  d_in[2];
    const float* selemb = (const float*)d_in[3];
    const float* W      = (const float*)d_in[4];
    const float* bias   = (const float*)d_in[5];
    float* out = (float*)d_out;

    cudaFuncSetAttribute(gemm_kernel,
                         cudaFuncAttributeMaxDynamicSharedMemorySize, DYNSM);

    init_kernel<<<1, 32>>>();
    split_x_kernel<<<(int)(((size_t)NB * KP + 255) / 256), 256>>>(X);
    dim3 wg((KP + 31) / 32, DM / 32, NE);
    split_w_kernel<<<wg, dim3(32, 8)>>>(W);
    phaseA_kernel<<<NB / 32, 1024>>>(logits, masks, selemb, out);
    guide_kernel<<<1, 512>>>(out);
    dim3 g(NB / 128, DM / 128, NE);
    gemm_kernel<<<g, 256, DYNSM>>>(bias);
    combine_kernel<<<(NB * DM / 4) / 256, 256>>>(out);
}